// round 6
// baseline (speedup 1.0000x reference)
#include <cuda_runtime.h>
#include <cuda_fp16.h>
#include <math.h>

// Problem constants
#define BATCH 32
#define CHAN  4
#define Hn    512
#define Wn    512
#define PLANE (Hn * Wn)

// Output layout (flattened tuple, fp32 elements):
#define kMatOff   33554432
#define kInvOff   33554720
#define kGridOff  33555008
#define kIGridOff 50332224

// NHWC fp16x4 packed copy of src: 32*512*512 px * 8B = 64 MB.
__device__ uint2 g_pack[BATCH * PLANE];

__global__ void build_mats_kernel(const float* __restrict__ fc2,
                                  float* __restrict__ out) {
    int b = threadIdx.x;
    if (b >= BATCH) return;
    const float PI = 3.14159265358979323846f;

    float f0 = fc2[b * 7 + 0];
    float f1 = fc2[b * 7 + 1];
    float f2 = fc2[b * 7 + 2];
    float f3 = fc2[b * 7 + 3];
    float f4 = fc2[b * 7 + 4];
    float f5 = fc2[b * 7 + 5];
    float f6 = fc2[b * 7 + 6];

    float theta = fminf(fmaxf(f0 * 0.3f, -1.0f), 1.0f) * PI;
    float sx    = fminf(fmaxf(f1 * 0.3f + 1.0f, 0.0f), 5.0f);
    float sy    = fminf(fmaxf(f2 * 0.3f + 1.0f, 0.0f), 5.0f);
    float tx    = f3 * 0.3f;
    float ty    = f4 * 0.3f;
    float shxy  = fminf(fmaxf(f5 * 0.3f, -1.0f), 1.0f) * PI;
    float shyx  = fminf(fmaxf(f6 * 0.3f, -1.0f), 1.0f) * PI;

    float c = cosf(theta);
    float s = sinf(theta);

    float m00 = sx * c + shxy * sy * s;
    float m01 = -sx * s + shxy * sy * c;
    float m10 = shyx * sx * c + sy * s;
    float m11 = -shyx * sx * s + sy * c;

    float det  = m00 * m11 - m01 * m10;
    float rdet = 1.0f / det;
    float i00 =  m11 * rdet;
    float i01 = -m01 * rdet;
    float i10 = -m10 * rdet;
    float i11 =  m00 * rdet;
    float i02 = (m01 * ty - m11 * tx) * rdet;
    float i12 = (m10 * tx - m00 * ty) * rdet;

    float* M = out + kMatOff + b * 9;
    M[0] = m00; M[1] = m01; M[2] = tx;
    M[3] = m10; M[4] = m11; M[5] = ty;
    M[6] = 0.0f; M[7] = 0.0f; M[8] = 1.0f;

    float* I = out + kInvOff + b * 9;
    I[0] = i00; I[1] = i01; I[2] = i02;
    I[3] = i10; I[4] = i11; I[5] = i12;
    I[6] = 0.0f; I[7] = 0.0f; I[8] = 1.0f;
}

// NCHW fp32 -> NHWC fp16x4, 4 pixels per thread (float4 loads, uint4 stores).
__global__ __launch_bounds__(256)
void pack_kernel(const float* __restrict__ src) {
    int t = blockIdx.x * 256 + threadIdx.x;
    int idx4 = t * 4;
    int b    = idx4 >> 18;
    int rem  = idx4 & (PLANE - 1);

    const float* base = src + (long long)b * CHAN * PLANE + rem;
    float4 v0 = __ldg(reinterpret_cast<const float4*>(base));
    float4 v1 = __ldg(reinterpret_cast<const float4*>(base + PLANE));
    float4 v2 = __ldg(reinterpret_cast<const float4*>(base + 2 * PLANE));
    float4 v3 = __ldg(reinterpret_cast<const float4*>(base + 3 * PLANE));

    uint2 p[4];
    {
        __half2 a, bb;
        a = __floats2half2_rn(v0.x, v1.x); bb = __floats2half2_rn(v2.x, v3.x);
        p[0].x = *reinterpret_cast<unsigned*>(&a); p[0].y = *reinterpret_cast<unsigned*>(&bb);
        a = __floats2half2_rn(v0.y, v1.y); bb = __floats2half2_rn(v2.y, v3.y);
        p[1].x = *reinterpret_cast<unsigned*>(&a); p[1].y = *reinterpret_cast<unsigned*>(&bb);
        a = __floats2half2_rn(v0.z, v1.z); bb = __floats2half2_rn(v2.z, v3.z);
        p[2].x = *reinterpret_cast<unsigned*>(&a); p[2].y = *reinterpret_cast<unsigned*>(&bb);
        a = __floats2half2_rn(v0.w, v1.w); bb = __floats2half2_rn(v2.w, v3.w);
        p[3].x = *reinterpret_cast<unsigned*>(&a); p[3].y = *reinterpret_cast<unsigned*>(&bb);
    }
    uint4* dst = reinterpret_cast<uint4*>(g_pack + idx4);
    dst[0] = make_uint4(p[0].x, p[0].y, p[1].x, p[1].y);
    dst[1] = make_uint4(p[2].x, p[2].y, p[3].x, p[3].y);
}

static __device__ __forceinline__ float4 unpack_h4(uint2 u) {
    __half2 lo = *reinterpret_cast<__half2*>(&u.x);
    __half2 hi = *reinterpret_cast<__half2*>(&u.y);
    float2 a = __half22float2(lo);
    float2 c = __half22float2(hi);
    return make_float4(a.x, a.y, c.x, c.y);
}

// Block tile: 32(x) x 8(y) pixels, 256 threads, 1 px/thread.
// Compute phase: ADAPTIVE warp footprint (16x2 / 8x4 / 4x8) chosen per block
// from the affine matrix to minimize L1 lines touched per gather instruction.
// Store phase: row-major float4 stores via smem staging (transformed) and
// affine recompute (grid/igrid).
__global__ __launch_bounds__(256)
void affine_main_kernel(float* __restrict__ out) {
    const int b  = blockIdx.z;
    const int bx = blockIdx.x * 32;
    const int by = blockIdx.y * 8;
    const int tid  = threadIdx.x;
    const int warp = tid >> 5;
    const int lane = tid & 31;

    __shared__ float sm[12];
    __shared__ float s_t[CHAN][8][32];  // XOR-swizzled columns

    if (tid < 6) {
        sm[tid]     = out[kMatOff + b * 9 + tid];
        sm[tid + 6] = out[kInvOff + b * 9 + tid];
    }
    __syncthreads();

    const float m00 = sm[0], m01 = sm[1], m02 = sm[2];
    const float m10 = sm[3], m11 = sm[4], m12 = sm[5];

    // ---- adaptive footprint selection (uniform across block) ----
    // d(ix)/dx = m00, d(ix)/dy = m01, d(iy)/dx = m10, d(iy)/dy = m11 (pixel units)
    int lw;
    {
        const float ax = fabsf(m00), ay = fabsf(m01);
        const float vx = fabsf(m10), vy = fabsf(m11);
        // lines(w,h) ~ (1 + (ax*w + ay*h)/16) * (2 + vx*w + vy*h)
        float c16 = (1.0f + (ax * 16.f + ay * 2.f) * 0.0625f) * (2.0f + vx * 16.f + vy * 2.f);
        float c8  = (1.0f + (ax *  8.f + ay * 4.f) * 0.0625f) * (2.0f + vx *  8.f + vy * 4.f);
        float c4  = (1.0f + (ax *  4.f + ay * 8.f) * 0.0625f) * (2.0f + vx *  4.f + vy * 8.f);
        lw = (c8 <= c16 && c8 <= c4) ? 3 : ((c16 <= c4) ? 4 : 2);
    }
    const int lh = 5 - lw;

    // ---- compute phase ----
    {
        const int lx = lane & ((1 << lw) - 1);
        const int ly = lane >> lw;
        const int wprl = 5 - lw;                    // log2(warps per tile-row)
        const int wx = (warp & ((1 << wprl) - 1)) << lw;
        const int wy = (warp >> wprl) << lh;
        const int cx = wx + lx;                     // col in tile 0..31
        const int cr = wy + ly;                     // row in tile 0..7
        const int x = bx + cx;
        const int y = by + cr;

        const float xp = (2.0f * (float)x + 1.0f) * (1.0f / (float)Wn) - 1.0f;
        const float yp = (2.0f * (float)y + 1.0f) * (1.0f / (float)Hn) - 1.0f;

        const float gx = fmaf(m00, xp, fmaf(m01, yp, m02));
        const float gy = fmaf(m10, xp, fmaf(m11, yp, m12));

        const float ix = gx * ((float)Wn * 0.5f) + ((float)Wn - 1.0f) * 0.5f;
        const float iy = gy * ((float)Hn * 0.5f) + ((float)Hn - 1.0f) * 0.5f;
        const float x0f = floorf(ix), y0f = floorf(iy);
        const float wxf = ix - x0f, wyf = iy - y0f;
        const int xi0 = (int)x0f, yi0 = (int)y0f;
        const int xi1 = xi0 + 1,  yi1 = yi0 + 1;

        const float vx0 = (xi0 >= 0 && xi0 < Wn) ? 1.0f : 0.0f;
        const float vx1 = (xi1 >= 0 && xi1 < Wn) ? 1.0f : 0.0f;
        const float vy0 = (yi0 >= 0 && yi0 < Hn) ? 1.0f : 0.0f;
        const float vy1 = (yi1 >= 0 && yi1 < Hn) ? 1.0f : 0.0f;

        const int cx0 = min(max(xi0, 0), Wn - 1);
        const int cx1 = min(max(xi1, 0), Wn - 1);
        const int cy0 = min(max(yi0, 0), Hn - 1);
        const int cy1 = min(max(yi1, 0), Hn - 1);

        const float w00 = (1.0f - wxf) * (1.0f - wyf) * vx0 * vy0;
        const float w01 = wxf * (1.0f - wyf) * vx1 * vy0;
        const float w10 = (1.0f - wxf) * wyf * vx0 * vy1;
        const float w11 = wxf * wyf * vx1 * vy1;

        const uint2* pk = g_pack + b * PLANE;
        float4 v00 = unpack_h4(__ldg(pk + cy0 * Wn + cx0));
        float4 v01 = unpack_h4(__ldg(pk + cy0 * Wn + cx1));
        float4 v10 = unpack_h4(__ldg(pk + cy1 * Wn + cx0));
        float4 v11 = unpack_h4(__ldg(pk + cy1 * Wn + cx1));

        const int sc = cx ^ ((cr & 3) << 3);  // swizzled column
        s_t[0][cr][sc] = fmaf(v00.x, w00, fmaf(v01.x, w01, fmaf(v10.x, w10, v11.x * w11)));
        s_t[1][cr][sc] = fmaf(v00.y, w00, fmaf(v01.y, w01, fmaf(v10.y, w10, v11.y * w11)));
        s_t[2][cr][sc] = fmaf(v00.z, w00, fmaf(v01.z, w01, fmaf(v10.z, w10, v11.z * w11)));
        s_t[3][cr][sc] = fmaf(v00.w, w00, fmaf(v01.w, w01, fmaf(v10.w, w10, v11.w * w11)));
    }
    __syncthreads();

    // ---- store phase: row-major float4 stores ----
    {
        const int ch  = tid >> 6;
        const int rem = tid & 63;
        const int row = rem >> 3;
        const int q   = rem & 7;
        const int scol = (q * 4) ^ ((row & 3) << 3);
        float4 v = *reinterpret_cast<const float4*>(&s_t[ch][row][scol]);
        int off = ((b * CHAN + ch) * Hn + (by + row)) * Wn + bx + q * 4;
        *reinterpret_cast<float4*>(out + off) = v;
    }

    // grid / inv_grid: recompute affine; threads 0-127 grid, 128-255 igrid.
    {
        const bool inv = tid >= 128;
        const float a00 = inv ? sm[6]  : m00;
        const float a01 = inv ? sm[7]  : m01;
        const float a02 = inv ? sm[8]  : m02;
        const float a10 = inv ? sm[9]  : m10;
        const float a11 = inv ? sm[10] : m11;
        const float a12 = inv ? sm[11] : m12;

        const int u   = tid & 127;
        const int row = u >> 4;
        const int col = (u & 15) * 2;

        const int x = bx + col;
        const int y = by + row;
        const float xp0 = (2.0f * (float)x + 1.0f) * (1.0f / (float)Wn) - 1.0f;
        const float xp1 = xp0 + 2.0f / (float)Wn;
        const float yp  = (2.0f * (float)y + 1.0f) * (1.0f / (float)Hn) - 1.0f;

        float4 g;
        g.x = fmaf(a00, xp0, fmaf(a01, yp, a02));
        g.y = fmaf(a10, xp0, fmaf(a11, yp, a12));
        g.z = fmaf(a00, xp1, fmaf(a01, yp, a02));
        g.w = fmaf(a10, xp1, fmaf(a11, yp, a12));

        const int pix = (b * Hn + y) * Wn + x;
        const int base = inv ? kIGridOff : kGridOff;
        *reinterpret_cast<float4*>(out + base + pix * 2) = g;
    }
}

extern "C" void kernel_launch(void* const* d_in, const int* in_sizes, int n_in,
                              void* d_out, int out_size) {
    const float* src = (const float*)d_in[0];
    const float* fc2 = (const float*)d_in[1];
    float* out = (float*)d_out;

    // Order: build first so ncu's skip-5 capture lands on affine_main_kernel.
    build_mats_kernel<<<1, 32>>>(fc2, out);
    pack_kernel<<<(BATCH * PLANE) / (256 * 4), 256>>>(src);

    dim3 grid(Wn / 32, Hn / 8, BATCH);
    affine_main_kernel<<<grid, 256>>>(out);
}